// round 1
// baseline (speedup 1.0000x reference)
#include <cuda_runtime.h>
#include <cuda_bf16.h>
#include <cstdint>

// Problem constants (from reference_code)
#define D_IN   128
#define D_OUT  128
#define K2     256   // 2*D_IN

// Scratch for the aggregated neighbor features (support = segment_sum)
// 100000 * 128 floats = 51.2 MB. Static __device__ array (no allocation allowed).
__device__ float g_support[100000 * D_IN];

// ---------------------------------------------------------------------------
// Kernel 1: zero the support scratch (float4 stores, HBM-write-bound ~7us)
// ---------------------------------------------------------------------------
__global__ void zero_support_kernel(int n4) {
    int i = blockIdx.x * blockDim.x + threadIdx.x;
    float4* p = reinterpret_cast<float4*>(g_support);
    if (i < n4) p[i] = make_float4(0.f, 0.f, 0.f, 0.f);
}

// ---------------------------------------------------------------------------
// Kernel 2: edge scatter.  One warp per edge: 32 lanes x float4 = 128 floats.
// gathered = x[src] * val;  support[dst] += gathered  via red.global.add.v4.f32
// ---------------------------------------------------------------------------
__global__ void scatter_kernel(const float* __restrict__ x,
                               const int*   __restrict__ esrc,
                               const int*   __restrict__ edst,
                               const float* __restrict__ eval_,
                               int E) {
    int warp = (blockIdx.x * blockDim.x + threadIdx.x) >> 5;
    int lane = threadIdx.x & 31;
    if (warp >= E) return;

    int   s = esrc[warp];
    int   d = edst[warp];
    float v = eval_[warp];

    const float4* xs = reinterpret_cast<const float4*>(x) + (size_t)s * (D_IN / 4);
    float4 xv = xs[lane];
    float4 r  = make_float4(xv.x * v, xv.y * v, xv.z * v, xv.w * v);

    float* p = g_support + (size_t)d * D_IN + lane * 4;
    asm volatile("red.global.add.v4.f32 [%0], {%1, %2, %3, %4};"
                 :: "l"(p), "f"(r.x), "f"(r.y), "f"(r.z), "f"(r.w)
                 : "memory");
}

// ---------------------------------------------------------------------------
// Kernel 3: out = [x, support] @ W + b
//   Block tile: 128 rows x 128 cols, 256 threads, 8x8 micro-tile per thread.
//   W is [256,128] row-major; k<128 reads x, k>=128 reads support (no concat
//   materialization).
// ---------------------------------------------------------------------------
#define TILE_K 16

__global__ __launch_bounds__(256)
void gemm_kernel(const float* __restrict__ x,
                 const float* __restrict__ W,
                 const float* __restrict__ bias,
                 float* __restrict__ out,
                 int N) {
    __shared__ float sW[TILE_K][128];   // W tile, same layout as global
    __shared__ float sH[TILE_K][128];   // H tile, transposed: sH[k][row_local]

    const int tid  = threadIdx.x;
    const int row0 = blockIdx.x * 128;
    const int col0 = (tid & 15) * 8;    // 16 thread-cols x 8
    const int r0   = (tid >> 4) * 8;    // 16 thread-rows x 8

    float acc[8][8];
#pragma unroll
    for (int i = 0; i < 8; i++)
#pragma unroll
        for (int j = 0; j < 8; j++) acc[i][j] = 0.f;

    // H-tile load indexing: 2 threads per row, 8 k-values each
    const int rl = tid >> 1;            // local row 0..127
    const int kh = (tid & 1) * 8;       // k-offset within tile: 0 or 8
    const int grow_ld = row0 + rl;

    for (int k0 = 0; k0 < K2; k0 += TILE_K) {
        // --- load W tile (2048 floats, coalesced float4 copy) ---
        {
            const float4* wg = reinterpret_cast<const float4*>(W + k0 * 128);
            float4* ws = reinterpret_cast<float4*>(&sW[0][0]);
            ws[tid]       = wg[tid];
            ws[tid + 256] = wg[tid + 256];
        }
        // --- load H tile transposed ---
        {
            float4 a, c;
            if (grow_ld < N) {
                const float* srcp = (k0 < D_IN)
                    ? (x         + (size_t)grow_ld * D_IN + k0 + kh)
                    : (g_support + (size_t)grow_ld * D_IN + (k0 - D_IN) + kh);
                a = *reinterpret_cast<const float4*>(srcp);
                c = *reinterpret_cast<const float4*>(srcp + 4);
            } else {
                a = make_float4(0.f, 0.f, 0.f, 0.f);
                c = a;
            }
            sH[kh + 0][rl] = a.x; sH[kh + 1][rl] = a.y;
            sH[kh + 2][rl] = a.z; sH[kh + 3][rl] = a.w;
            sH[kh + 4][rl] = c.x; sH[kh + 5][rl] = c.y;
            sH[kh + 6][rl] = c.z; sH[kh + 7][rl] = c.w;
        }
        __syncthreads();

#pragma unroll
        for (int kk = 0; kk < TILE_K; kk++) {
            float4 w0 = *reinterpret_cast<float4*>(&sW[kk][col0]);
            float4 w1 = *reinterpret_cast<float4*>(&sW[kk][col0 + 4]);
            float4 h0 = *reinterpret_cast<float4*>(&sH[kk][r0]);
            float4 h1 = *reinterpret_cast<float4*>(&sH[kk][r0 + 4]);
            float wv[8] = {w0.x, w0.y, w0.z, w0.w, w1.x, w1.y, w1.z, w1.w};
            float hv[8] = {h0.x, h0.y, h0.z, h0.w, h1.x, h1.y, h1.z, h1.w};
#pragma unroll
            for (int i = 0; i < 8; i++)
#pragma unroll
                for (int j = 0; j < 8; j++)
                    acc[i][j] += hv[i] * wv[j];
        }
        __syncthreads();
    }

    // --- epilogue: add bias, store float4 ---
    float bb[8];
#pragma unroll
    for (int j = 0; j < 8; j++) bb[j] = bias[col0 + j];

#pragma unroll
    for (int i = 0; i < 8; i++) {
        int grow = row0 + r0 + i;
        if (grow < N) {
            float4 o0 = make_float4(acc[i][0] + bb[0], acc[i][1] + bb[1],
                                    acc[i][2] + bb[2], acc[i][3] + bb[3]);
            float4 o1 = make_float4(acc[i][4] + bb[4], acc[i][5] + bb[5],
                                    acc[i][6] + bb[6], acc[i][7] + bb[7]);
            float* op = out + (size_t)grow * D_OUT + col0;
            *reinterpret_cast<float4*>(op)     = o0;
            *reinterpret_cast<float4*>(op + 4) = o1;
        }
    }
}

// ---------------------------------------------------------------------------
// Launch
// ---------------------------------------------------------------------------
extern "C" void kernel_launch(void* const* d_in, const int* in_sizes, int n_in,
                              void* d_out, int out_size) {
    const float* x     = (const float*)d_in[0];
    const int*   esrc  = (const int*)  d_in[1];
    const int*   edst  = (const int*)  d_in[2];
    const float* eval_ = (const float*)d_in[3];
    const float* W     = (const float*)d_in[4];
    const float* bias  = (const float*)d_in[5];
    float*       out   = (float*)d_out;

    const int N = in_sizes[0] / D_IN;     // 100000
    const int E = in_sizes[1];            // 1600000

    // 1) zero support scratch
    {
        int n4 = N * (D_IN / 4);
        int threads = 256;
        int blocks = (n4 + threads - 1) / threads;
        zero_support_kernel<<<blocks, threads>>>(n4);
    }
    // 2) scatter (one warp per edge)
    {
        int warps_per_block = 8;                   // 256 threads
        int blocks = (E + warps_per_block - 1) / warps_per_block;
        scatter_kernel<<<blocks, 256>>>(x, esrc, edst, eval_, E);
    }
    // 3) GEMM + bias
    {
        int blocks = (N + 127) / 128;              // 782
        gemm_kernel<<<blocks, 256>>>(x, W, bias, out, N);
    }
}

// round 3
// speedup vs baseline: 1.4158x; 1.4158x over previous
#include <cuda_runtime.h>
#include <cuda_bf16.h>
#include <cstdint>

#define D      128      // D_IN = D_OUT
#define NMAX   100000

// Scratch (device globals; no allocation allowed)
__device__ __nv_bfloat16 g_xh[NMAX * D];   // x hi (bf16)
__device__ __nv_bfloat16 g_xl[NMAX * D];   // x lo (residual bf16)
__device__ float         g_y [NMAX * D];   // y = x @ W2

// ============================================================================
// PTX helpers (base-ISA only: cp.async / ldmatrix / mma.sync — no tcgen05!)
// ============================================================================
__device__ __forceinline__ uint32_t smem_to_u32(const void* p) {
    uint32_t a;
    asm("{ .reg .u64 t; cvta.to.shared.u64 t, %1; cvt.u32.u64 %0, t; }"
        : "=r"(a) : "l"(p));
    return a;
}
#define CP_ASYNC16(dst, src, sz) \
    asm volatile("cp.async.cg.shared.global [%0], [%1], 16, %2;" \
        :: "r"(dst), "l"(src), "r"(sz))
#define CP_COMMIT() asm volatile("cp.async.commit_group;" ::: "memory")
#define CP_WAIT1()  asm volatile("cp.async.wait_group 1;"  ::: "memory")

#define LDSM_X4(r0,r1,r2,r3,addr) \
    asm volatile("ldmatrix.sync.aligned.m8n8.x4.shared.b16 {%0,%1,%2,%3}, [%4];" \
        : "=r"(r0), "=r"(r1), "=r"(r2), "=r"(r3) : "r"(addr))
#define LDSM_X4T(r0,r1,r2,r3,addr) \
    asm volatile("ldmatrix.sync.aligned.m8n8.x4.trans.shared.b16 {%0,%1,%2,%3}, [%4];" \
        : "=r"(r0), "=r"(r1), "=r"(r2), "=r"(r3) : "r"(addr))

#define MMA16816(c, a, b) \
    asm volatile("mma.sync.aligned.m16n8k16.row.col.f32.bf16.bf16.f32 " \
        "{%0,%1,%2,%3}, {%4,%5,%6,%7}, {%8,%9}, {%0,%1,%2,%3};" \
        : "+f"((c)[0]), "+f"((c)[1]), "+f"((c)[2]), "+f"((c)[3]) \
        : "r"((a)[0]), "r"((a)[1]), "r"((a)[2]), "r"((a)[3]), \
          "r"((b)[0]), "r"((b)[1]))

// ============================================================================
// Kernel 1: split x into bf16 hi/lo (one pass)
// ============================================================================
__global__ void convert_kernel(const float* __restrict__ x, int n4) {
    int i = blockIdx.x * blockDim.x + threadIdx.x;
    if (i >= n4) return;
    float4 v = reinterpret_cast<const float4*>(x)[i];
    __nv_bfloat162 h0 = __floats2bfloat162_rn(v.x, v.y);
    __nv_bfloat162 h1 = __floats2bfloat162_rn(v.z, v.w);
    float r0 = v.x - __bfloat162float(h0.x);
    float r1 = v.y - __bfloat162float(h0.y);
    float r2 = v.z - __bfloat162float(h1.x);
    float r3 = v.w - __bfloat162float(h1.y);
    __nv_bfloat162 l0 = __floats2bfloat162_rn(r0, r1);
    __nv_bfloat162 l1 = __floats2bfloat162_rn(r2, r3);
    uint2 hw = make_uint2(*(uint32_t*)&h0, *(uint32_t*)&h1);
    uint2 lw = make_uint2(*(uint32_t*)&l0, *(uint32_t*)&l1);
    reinterpret_cast<uint2*>(g_xh)[i] = hw;
    reinterpret_cast<uint2*>(g_xl)[i] = lw;
}

// ============================================================================
// Kernel 2: persistent split-bf16 GEMM via mma.sync
//   Work item (m_tile, nh):  nh=0 -> d_out = x@W1 + b ;  nh=1 -> g_y = x@W2
//   CTA tile 128(M) x 128(N), K=128 full.  8 warps, warp tile 32M x 64N.
//   SMEM: A double-buffered hi/lo (4 x 32KB) + B hi/lo (2 x 32KB) = 192KB.
// ============================================================================
#define GT 256
#define AS_OFF(buf,hl) ((uint32_t)(((buf)<<1 | (hl)) * 32768))
#define BS_OFF(hl)     ((uint32_t)(131072 + (hl) * 32768))
#define SM_TOTAL       196608

__device__ __forceinline__ void load_A_tile(uint32_t smem_base, int buf,
                                            int node0, int N, int tid) {
#pragma unroll
    for (int i = 0; i < 8; i++) {
        int idx  = tid + (i << 8);        // 0..2047
        int row  = idx >> 4;              // 0..127
        int cc   = idx & 15;              // 16B chunk within row
        int node = node0 + row;
        uint32_t sz    = (node < N) ? 16u : 0u;
        uint32_t chunk = (uint32_t)(cc ^ (row & 7));
        uint32_t doff  = (uint32_t)row * 256u + chunk * 16u;
        const __nv_bfloat16* sh = g_xh + (size_t)node * D + cc * 8;
        const __nv_bfloat16* sl = g_xl + (size_t)node * D + cc * 8;
        CP_ASYNC16(smem_base + AS_OFF(buf, 0) + doff, sh, sz);
        CP_ASYNC16(smem_base + AS_OFF(buf, 1) + doff, sl, sz);
    }
}

__global__ __launch_bounds__(GT, 1)
void gemm_kernel(const float* __restrict__ W,
                 const float* __restrict__ bias,
                 float* __restrict__ out,
                 int N) {
    extern __shared__ char smem[];
    uint32_t smem_base = smem_to_u32(smem);
    const int tid  = threadIdx.x;
    const int lane = tid & 31;
    const int wid  = tid >> 5;
    const int warp_m = (wid & 3) << 5;     // 0,32,64,96
    const int warp_n = (wid >> 2) << 6;    // 0,64

    const int num_tiles = (N + 127) >> 7;
    const int total = num_tiles * 2;
    int cur_nh = -1;

    int item = blockIdx.x;
    int buf = 0;
    if (item < total) load_A_tile(smem_base, 0, (item % num_tiles) << 7, N, tid);
    CP_COMMIT();

    for (; item < total; item += gridDim.x) {
        const int m_tile = item % num_tiles;
        const int nh     = item / num_tiles;
        const int node0  = m_tile << 7;

        // prefetch next tile's A into the other buffer
        int next = item + gridDim.x;
        if (next < total)
            load_A_tile(smem_base, buf ^ 1, (next % num_tiles) << 7, N, tid);
        CP_COMMIT();

        // (re)load B = W[nh*128 : nh*128+128][:] as bf16 hi/lo into smem
        if (nh != cur_nh) {
            cur_nh = nh;
#pragma unroll
            for (int j = 0; j < 32; j++) {
                int idx = tid + (j << 8);          // 0..8191 (bf16x2 pairs)
                int k   = idx >> 6;                // 0..127
                int n   = (idx & 63) << 1;         // even col
                const float* wp = W + ((size_t)(nh * 128 + k)) * 128 + n;
                float w0 = wp[0], w1 = wp[1];
                __nv_bfloat162 h = __floats2bfloat162_rn(w0, w1);
                float q0 = w0 - __bfloat162float(h.x);
                float q1 = w1 - __bfloat162float(h.y);
                __nv_bfloat162 l = __floats2bfloat162_rn(q0, q1);
                uint32_t boff = (uint32_t)k * 256u
                              + (uint32_t)(((n >> 3) ^ (k & 7)) << 4)
                              + (uint32_t)((n & 7) << 1);
                *reinterpret_cast<uint32_t*>(smem + BS_OFF(0) + boff) = *(uint32_t*)&h;
                *reinterpret_cast<uint32_t*>(smem + BS_OFF(1) + boff) = *(uint32_t*)&l;
            }
        }

        CP_WAIT1();
        __syncthreads();     // A(buf) ready + B visible

        // ---- compute: K=128 in 8 k-steps of 16 ----
        float acc[2][8][4];
#pragma unroll
        for (int mi = 0; mi < 2; mi++)
#pragma unroll
            for (int ni = 0; ni < 8; ni++)
#pragma unroll
                for (int q = 0; q < 4; q++) acc[mi][ni][q] = 0.f;

#pragma unroll
        for (int ks = 0; ks < 8; ks++) {
            uint32_t ah[2][4], al[2][4];
#pragma unroll
            for (int mi = 0; mi < 2; mi++) {
                int row = warp_m + (mi << 4) + (lane & 15);
                int cb  = (ks << 1) + (lane >> 4);
                uint32_t addr = smem_base + AS_OFF(buf, 0)
                              + (uint32_t)row * 256u
                              + (uint32_t)((cb ^ (row & 7)) << 4);
                LDSM_X4(ah[mi][0], ah[mi][1], ah[mi][2], ah[mi][3], addr);
                LDSM_X4(al[mi][0], al[mi][1], al[mi][2], al[mi][3], addr + 32768u);
            }
            uint32_t bh[8][2], bl[8][2];
#pragma unroll
            for (int nj = 0; nj < 4; nj++) {
                int row = (ks << 4) + (lane & 15);
                int cb  = (warp_n >> 3) + (nj << 1) + (lane >> 4);
                uint32_t addr = smem_base + BS_OFF(0)
                              + (uint32_t)row * 256u
                              + (uint32_t)((cb ^ (row & 7)) << 4);
                LDSM_X4T(bh[2*nj][0], bh[2*nj][1], bh[2*nj+1][0], bh[2*nj+1][1], addr);
                LDSM_X4T(bl[2*nj][0], bl[2*nj][1], bl[2*nj+1][0], bl[2*nj+1][1],
                         addr + 32768u);
            }
#pragma unroll
            for (int mi = 0; mi < 2; mi++)
#pragma unroll
                for (int ni = 0; ni < 8; ni++) {
                    MMA16816(acc[mi][ni], ah[mi], bh[ni]);   // Ah*Bh
                    MMA16816(acc[mi][ni], ah[mi], bl[ni]);   // Ah*Bl
                    MMA16816(acc[mi][ni], al[mi], bh[ni]);   // Al*Bh
                }
        }

        // ---- epilogue ----
        float* dst = (nh == 0) ? out : g_y;
#pragma unroll
        for (int ni = 0; ni < 8; ni++) {
            int col = warp_n + (ni << 3) + ((lane & 3) << 1);
            float b0 = 0.f, b1 = 0.f;
            if (nh == 0) { b0 = bias[col]; b1 = bias[col + 1]; }
#pragma unroll
            for (int mi = 0; mi < 2; mi++) {
                int r = warp_m + (mi << 4) + (lane >> 2);
                int node = node0 + r;
                if (node < N) {
                    float2 v = make_float2(acc[mi][ni][0] + b0, acc[mi][ni][1] + b1);
                    *reinterpret_cast<float2*>(dst + (size_t)node * D + col) = v;
                }
                int node2 = node + 8;
                if (node2 < N) {
                    float2 v = make_float2(acc[mi][ni][2] + b0, acc[mi][ni][3] + b1);
                    *reinterpret_cast<float2*>(dst + (size_t)node2 * D + col) = v;
                }
            }
        }
        __syncthreads();     // protect buf before it is refilled next iter
        buf ^= 1;
    }
}

// ============================================================================
// Kernel 3: edge scatter:  out[dst] += val * y[src]   (warp per edge)
// ============================================================================
__global__ void scatter_kernel(const int*   __restrict__ esrc,
                               const int*   __restrict__ edst,
                               const float* __restrict__ eval_,
                               float* __restrict__ out,
                               int E) {
    int warp = (blockIdx.x * blockDim.x + threadIdx.x) >> 5;
    int lane = threadIdx.x & 31;
    if (warp >= E) return;

    int   s = esrc[warp];
    int   d = edst[warp];
    float v = eval_[warp];

    const float4* ys = reinterpret_cast<const float4*>(g_y) + (size_t)s * (D / 4);
    float4 yv = ys[lane];
    float4 r  = make_float4(yv.x * v, yv.y * v, yv.z * v, yv.w * v);

    float* p = out + (size_t)d * D + lane * 4;
    asm volatile("red.global.add.v4.f32 [%0], {%1, %2, %3, %4};"
                 :: "l"(p), "f"(r.x), "f"(r.y), "f"(r.z), "f"(r.w)
                 : "memory");
}

// ============================================================================
// Launch
// ============================================================================
extern "C" void kernel_launch(void* const* d_in, const int* in_sizes, int n_in,
                              void* d_out, int out_size) {
    const float* x     = (const float*)d_in[0];
    const int*   esrc  = (const int*)  d_in[1];
    const int*   edst  = (const int*)  d_in[2];
    const float* eval_ = (const float*)d_in[3];
    const float* W     = (const float*)d_in[4];
    const float* bias  = (const float*)d_in[5];
    float*       out   = (float*)d_out;

    const int N = in_sizes[0] / D;     // 100000
    const int E = in_sizes[1];         // 1600000

    // 1) split x -> bf16 hi/lo
    {
        int n4 = N * (D / 4);
        convert_kernel<<<(n4 + 255) / 256, 256>>>(x, n4);
    }
    // 2) persistent GEMM: d_out = x@W1 + b ; g_y = x@W2
    {
        static bool attr_set = false;
        if (!attr_set) {
            cudaFuncSetAttribute(gemm_kernel,
                                 cudaFuncAttributeMaxDynamicSharedMemorySize,
                                 SM_TOTAL);
            attr_set = true;
        }
        gemm_kernel<<<148, GT, SM_TOTAL>>>(W, bias, out, N);
    }
    // 3) scatter-add edges into d_out
    {
        int blocks = (E + 7) / 8;      // 8 warps per block
        scatter_kernel<<<blocks, 256>>>(esrc, edst, eval_, out, E);
    }
}